// round 4
// baseline (speedup 1.0000x reference)
#include <cuda_runtime.h>
#include <cstdint>

// Problem constants (fixed shapes from setup_inputs)
#define LSEQ 2048
#define HDIM 1024
#define EDIM 1024
#define GB 128          // persistent blocks (1 per SM, all co-resident)
#define TB 256          // threads per persistent block
#define HPB 8           // h elements owned per block (128*8 = 1024)

// ---------------- scratch (static device globals; no dynamic alloc) ----------------
__device__ float g_target[EDIM];
__device__ float g_zc[2][4 * HDIM];   // w_ih@target + b_ih + b_hh per direction
__device__ float g_zf[2][4 * HDIM];   // w_ih@seq[first] + b_ih + b_hh per direction
__device__ int   g_meta[4];           // {fl_step, fl_tok, fr_step, fr_tok}
__device__ __align__(16) float g_hbuf[2][HDIM];              // ping-pong h
__device__ unsigned g_tag[GB];                                // per-block progress tag
__device__ __align__(16) float g_hsl [(size_t)LSEQ * HDIM];  // left-pass hiddens (8 MB)
__device__ __align__(16) float g_prod[(size_t)LSEQ * HDIM];  // hs_l * hs_r       (8 MB)
__device__ float g_beta[LSEQ];
__device__ float g_alfa[LSEQ];
__device__ float g_s[HDIM];

// ---------------- math helpers ----------------
__device__ __forceinline__ float sigf(float x)     { return 1.0f / (1.0f + __expf(-x)); }
__device__ __forceinline__ float tanhfast(float x) { return 1.0f - 2.0f / (1.0f + __expf(2.0f * x)); }
__device__ __forceinline__ unsigned ld_acq(const unsigned* p) {
    unsigned v;
    asm volatile("ld.acquire.gpu.u32 %0, [%1];" : "=r"(v) : "l"(p) : "memory");
    return v;
}
__device__ __forceinline__ void st_rel(unsigned* p, unsigned v) {
    asm volatile("st.release.gpu.u32 [%0], %1;" :: "l"(p), "r"(v) : "memory");
}
// packed f32x2 FMA (Blackwell): d = a*b + c elementwise on 2 packed floats
__device__ __forceinline__ unsigned long long ffma2(unsigned long long a,
                                                    unsigned long long b,
                                                    unsigned long long c) {
    unsigned long long d;
    asm("fma.rn.f32x2 %0, %1, %2, %3;" : "=l"(d) : "l"(a), "l"(b), "l"(c));
    return d;
}
__device__ __forceinline__ float2 unpack2(unsigned long long v) {
    float2 f;
    asm("mov.b64 {%0, %1}, %2;" : "=f"(f.x), "=f"(f.y) : "l"(v));
    return f;
}

// ---------------- kernel A: target mean, meta scalars, init tags/buffers ----------------
__global__ void prep_kernel(const int* __restrict__ x, const int* __restrict__ ts,
                            const int* __restrict__ te, const float* __restrict__ emb) {
    int start = ts[0], end = te[0];
    int tid = blockIdx.x * blockDim.x + threadIdx.x;   // 0..1023
    float s = 0.0f;
    for (int t = start; t <= end; t++)
        s += emb[(size_t)x[t] * EDIM + tid];
    g_target[tid] = s / (float)(end - start + 1);
    g_beta[tid] = 0.0f;
    g_beta[1024 + tid] = 0.0f;
    g_s[tid] = 0.0f;
    g_hbuf[0][tid] = 0.0f;          // step-0 input h = 0
    if (tid < GB) g_tag[tid] = 0;   // step-0 input ready
    if (tid == 0) {
        int fl = (start > 0) ? 0 : (end + 1);
        g_meta[0] = (fl < LSEQ) ? fl : -1;
        g_meta[1] = (fl < LSEQ) ? fl : 0;
        int frs, frt;
        if (end < LSEQ - 1)      { frs = 0;            frt = LSEQ - 1;  }
        else if (start > 0)      { frs = LSEQ - start; frt = start - 1; }
        else                     { frs = -1;           frt = 0;         }
        g_meta[2] = frs; g_meta[3] = frt;
    }
}

// ---------------- kernel B: z vectors (4 matvecs 4096x1024), one block per output row ----
__global__ void zvec_kernel(const int* __restrict__ x, const float* __restrict__ emb,
                            const float* __restrict__ wil, const float* __restrict__ bil,
                            const float* __restrict__ bhl,
                            const float* __restrict__ wir, const float* __restrict__ bir,
                            const float* __restrict__ bhr) {
    int bid = blockIdx.x;
    int dir = bid >> 12;           // 0: left, 1: right
    int row = bid & 4095;
    const float* wi = dir ? wir : wil;
    const float* bi = dir ? bir : bil;
    const float* bh = dir ? bhr : bhl;
    int tokpos = dir ? g_meta[3] : g_meta[1];
    int tok = x[tokpos];
    const float* wrow = wi + (size_t)row * EDIM;
    const float* trow = emb + (size_t)tok * EDIM;
    int tid = threadIdx.x;
    float sc = 0.0f, sf = 0.0f;
    for (int e = tid; e < EDIM; e += 128) {
        float wv = wrow[e];
        sc += wv * g_target[e];
        sf += wv * trow[e];
    }
    #pragma unroll
    for (int off = 16; off; off >>= 1) {
        sc += __shfl_xor_sync(0xffffffffu, sc, off);
        sf += __shfl_xor_sync(0xffffffffu, sf, off);
    }
    __shared__ float r1[4], r2[4];
    int wid = tid >> 5, lane = tid & 31;
    if (lane == 0) { r1[wid] = sc; r2[wid] = sf; }
    __syncthreads();
    if (tid == 0) {
        float bb = bi[row] + bh[row];
        g_zc[dir][row] = r1[0] + r1[1] + r1[2] + r1[3] + bb;
        g_zf[dir][row] = r2[0] + r2[1] + r2[2] + r2[3] + bb;
    }
}

// ---------------- kernel C: persistent LSTM recurrence (both directions) ----------------
// 128 blocks x 256 threads, all resident. Weights in registers as packed f32x2 pairs.
// Dataflow sync: ping-pong h buffers + per-block release-tag; skew provably <= 1 step.
__global__ void __launch_bounds__(TB, 1)
lstm_kernel(const float* __restrict__ whl, const float* __restrict__ whr) {
    __shared__ float rs[32];
    __shared__ float zc_s[32], zf_s[32];
    __shared__ float c_s[HPB];
    __shared__ __align__(16) float sm_h[HDIM];

    const int tid  = threadIdx.x;
    const int lane = tid & 31;
    const int w    = tid >> 5;
    const int hbase = blockIdx.x * HPB;

    if (tid < HPB) c_s[tid] = 0.0f;

    ulonglong2 wv[4][8];
    for (int dir = 0; dir < 2; dir++) {
        const float* W = dir ? whr : whl;
        // load this thread's 128 weights into registers (as packed pairs)
        #pragma unroll
        for (int r = 0; r < 4; r++) {
            int lr = 4 * w + r;
            int q = lr >> 3, k = lr & 7;
            const ulonglong2* wrow =
                (const ulonglong2*)(W + (size_t)(q * HDIM + hbase + k) * HDIM);
            #pragma unroll
            for (int j = 0; j < 8; j++) wv[r][j] = wrow[j * 32 + lane];
        }
        if (tid < 32) {
            int q = tid >> 3, k = tid & 7;
            zc_s[tid] = g_zc[dir][q * HDIM + hbase + k];
            zf_s[tid] = g_zf[dir][q * HDIM + hbase + k];
        }
        const int special = dir ? g_meta[2] : g_meta[0];
        __syncthreads();

        for (int step = 0; step < LSEQ; step++) {
            const unsigned g = (unsigned)(dir * LSEQ + step);

            // wait until every block published its h segment for step g
            if (tid < GB) { while (ld_acq(&g_tag[tid]) < g) {} }
            __syncthreads();

            // stage h into SMEM (4 KB from L2 per block, once)
            {
                float4 v = __ldcg(&((const float4*)g_hbuf[g & 1u])[tid]);
                ((float4*)sm_h)[tid] = v;
            }
            __syncthreads();

            // 4 gate-rows per warp: packed-FMA dot products over SMEM h
            const ulonglong2* hp = (const ulonglong2*)sm_h;
            ulonglong2 hv[8];
            #pragma unroll
            for (int j = 0; j < 8; j++) hv[j] = hp[j * 32 + lane];

            #pragma unroll
            for (int r = 0; r < 4; r++) {
                unsigned long long a0 = 0ull, a1 = 0ull;
                #pragma unroll
                for (int j = 0; j < 8; j++) {
                    a0 = ffma2(wv[r][j].x, hv[j].x, a0);
                    a1 = ffma2(wv[r][j].y, hv[j].y, a1);
                }
                float2 p = unpack2(a0), q2 = unpack2(a1);
                float a = (p.x + p.y) + (q2.x + q2.y);
                #pragma unroll
                for (int off = 16; off; off >>= 1)
                    a += __shfl_xor_sync(0xffffffffu, a, off);
                if (lane == 0) rs[4 * w + r] = a;
            }
            __syncthreads();

            if (tid < HPB) {
                const float* z = (step == special) ? zf_s : zc_s;
                int k = tid;
                float pi = rs[k]      + z[k];
                float pf = rs[8 + k]  + z[8 + k];
                float pg = rs[16 + k] + z[16 + k];
                float po = rs[24 + k] + z[24 + k];
                float gi = sigf(pi), gf = sigf(pf), gg = tanhfast(pg), go = sigf(po);
                float c = gf * c_s[k] + gi * gg;
                c_s[k] = c;
                float h = go * tanhfast(c);
                __stcg(&g_hbuf[(g + 1u) & 1u][hbase + k], h);
                size_t off = (size_t)step * HDIM + hbase + k;
                if (dir == 0) g_hsl[off] = h;
                else          g_prod[off] = h * g_hsl[off];
            }
            __syncthreads();                 // order h stores before the tag release
            if (tid == 0) st_rel(&g_tag[blockIdx.x], g + 1u);
        }
        __syncthreads();
    }
}

// ---------------- kernel D: beta[t] = sum_j u[j]*tanh(lin1_w[j,:]·prod[t,:] + b[j]) ------
__global__ void beta_kernel(const float* __restrict__ l1w, const float* __restrict__ l1b,
                            const float* __restrict__ u) {
    __shared__ float sA[32][33];
    __shared__ __align__(16) float sBT[32][128];
    __shared__ float red[8][32];

    const int tid = threadIdx.x;
    const int t0 = blockIdx.x * 32;
    const int j0 = blockIdx.y * 128;
    const int t  = tid & 31;
    const int jg = tid >> 5;

    float acc[16];
    #pragma unroll
    for (int m = 0; m < 16; m++) acc[m] = 0.0f;

    const float4* prod4 = (const float4*)g_prod;

    for (int kc = 0; kc < HDIM; kc += 32) {
        {
            int tl = tid >> 3;
            int k0 = (tid & 7) * 4;
            float4 v = prod4[(size_t)(t0 + tl) * 256 + (kc >> 2) + (tid & 7)];
            sA[tl][k0 + 0] = v.x; sA[tl][k0 + 1] = v.y;
            sA[tl][k0 + 2] = v.z; sA[tl][k0 + 3] = v.w;
        }
        {
            int jj = tid >> 1;
            int koff = (tid & 1) * 16;
            const float4* wr = (const float4*)(l1w + (size_t)(j0 + jj) * HDIM + kc + koff);
            #pragma unroll
            for (int q4 = 0; q4 < 4; q4++) {
                float4 v = wr[q4];
                sBT[koff + q4 * 4 + 0][jj] = v.x;
                sBT[koff + q4 * 4 + 1][jj] = v.y;
                sBT[koff + q4 * 4 + 2][jj] = v.z;
                sBT[koff + q4 * 4 + 3][jj] = v.w;
            }
        }
        __syncthreads();
        #pragma unroll 8
        for (int k = 0; k < 32; k++) {
            float a = sA[t][k];
            const float4* brow = (const float4*)(&sBT[k][jg * 16]);
            float4 b0 = brow[0], b1 = brow[1], b2 = brow[2], b3 = brow[3];
            acc[0]  += a * b0.x; acc[1]  += a * b0.y; acc[2]  += a * b0.z; acc[3]  += a * b0.w;
            acc[4]  += a * b1.x; acc[5]  += a * b1.y; acc[6]  += a * b1.z; acc[7]  += a * b1.w;
            acc[8]  += a * b2.x; acc[9]  += a * b2.y; acc[10] += a * b2.z; acc[11] += a * b2.w;
            acc[12] += a * b3.x; acc[13] += a * b3.y; acc[14] += a * b3.z; acc[15] += a * b3.w;
        }
        __syncthreads();
    }

    float partial = 0.0f;
    #pragma unroll
    for (int m = 0; m < 16; m++) {
        int j = j0 + jg * 16 + m;
        float val = acc[m] + l1b[j];
        partial += tanhfast(val) * u[j];
    }
    red[jg][t] = partial;
    __syncthreads();
    if (tid < 32) {
        float s = 0.0f;
        #pragma unroll
        for (int g2 = 0; g2 < 8; g2++) s += red[g2][tid];
        atomicAdd(&g_beta[t0 + tid], s);
    }
}

// ---------------- kernel E: softmax over beta[2048] -> alfa ----------------
__global__ void softmax_kernel() {
    __shared__ float sm[256];
    int tid = threadIdx.x;
    float v[8];
    float mx = -1e30f;
    #pragma unroll
    for (int i = 0; i < 8; i++) { v[i] = g_beta[tid * 8 + i]; mx = fmaxf(mx, v[i]); }
    sm[tid] = mx; __syncthreads();
    for (int s = 128; s; s >>= 1) { if (tid < s) sm[tid] = fmaxf(sm[tid], sm[tid + s]); __syncthreads(); }
    mx = sm[0]; __syncthreads();
    float sum = 0.0f;
    #pragma unroll
    for (int i = 0; i < 8; i++) { v[i] = __expf(v[i] - mx); sum += v[i]; }
    sm[tid] = sum; __syncthreads();
    for (int s = 128; s; s >>= 1) { if (tid < s) sm[tid] += sm[tid + s]; __syncthreads(); }
    float inv = 1.0f / sm[0];
    #pragma unroll
    for (int i = 0; i < 8; i++) g_alfa[tid * 8 + i] = v[i] * inv;
}

// ---------------- kernel F: s[j] = sum_t alfa[t] * prod[t,j] ----------------
__global__ void sred_kernel() {
    int tid = threadIdx.x;
    int t0 = blockIdx.x * 64;
    float4 acc = make_float4(0.f, 0.f, 0.f, 0.f);
    const float4* p4 = (const float4*)g_prod;
    for (int t = 0; t < 64; t++) {
        float a = g_alfa[t0 + t];
        float4 p = p4[(size_t)(t0 + t) * 256 + tid];
        acc.x += a * p.x; acc.y += a * p.y; acc.z += a * p.z; acc.w += a * p.w;
    }
    atomicAdd(&g_s[tid * 4 + 0], acc.x);
    atomicAdd(&g_s[tid * 4 + 1], acc.y);
    atomicAdd(&g_s[tid * 4 + 2], acc.z);
    atomicAdd(&g_s[tid * 4 + 3], acc.w);
}

// ---------------- kernel G: out[p] = s · lin2_w[p,:] + lin2_b[p], p=0..2 ----------------
__global__ void final_kernel(const float* __restrict__ l2w, const float* __restrict__ l2b,
                             float* __restrict__ out) {
    int wp = threadIdx.x >> 5, lane = threadIdx.x & 31;
    if (wp < 3) {
        float s = 0.0f;
        for (int j = lane; j < HDIM; j += 32)
            s += g_s[j] * l2w[wp * HDIM + j];
        #pragma unroll
        for (int off = 16; off; off >>= 1) s += __shfl_xor_sync(0xffffffffu, s, off);
        if (lane == 0) out[wp] = s + l2b[wp];
    }
}

// ---------------- launch ----------------
extern "C" void kernel_launch(void* const* d_in, const int* in_sizes, int n_in,
                              void* d_out, int out_size) {
    (void)in_sizes; (void)n_in; (void)out_size;
    const int*   x   = (const int*)d_in[0];
    const int*   ts  = (const int*)d_in[1];
    const int*   te  = (const int*)d_in[2];
    const float* emb = (const float*)d_in[3];
    const float* wil = (const float*)d_in[4];
    const float* whl = (const float*)d_in[5];
    const float* bil = (const float*)d_in[6];
    const float* bhl = (const float*)d_in[7];
    const float* wir = (const float*)d_in[8];
    const float* whr = (const float*)d_in[9];
    const float* bir = (const float*)d_in[10];
    const float* bhr = (const float*)d_in[11];
    const float* l1w = (const float*)d_in[12];
    const float* l1b = (const float*)d_in[13];
    const float* u   = (const float*)d_in[14];
    const float* l2w = (const float*)d_in[15];
    const float* l2b = (const float*)d_in[16];
    float* out = (float*)d_out;

    prep_kernel<<<8, 128>>>(x, ts, te, emb);
    zvec_kernel<<<8192, 128>>>(x, emb, wil, bil, bhl, wir, bir, bhr);
    lstm_kernel<<<GB, TB>>>(whl, whr);
    beta_kernel<<<dim3(LSEQ / 32, HDIM / 128), 256>>>(l1w, l1b, u);
    softmax_kernel<<<1, 256>>>();
    sred_kernel<<<32, 256>>>();
    final_kernel<<<1, 128>>>(l2w, l2b, out);
}

// round 5
// speedup vs baseline: 2.9838x; 2.9838x over previous
#include <cuda_runtime.h>
#include <cstdint>

// Problem constants (fixed shapes from setup_inputs)
#define LSEQ 2048
#define HDIM 1024
#define EDIM 1024
#define GB 128          // persistent blocks (1 per SM, all co-resident)
#define TB 256          // threads per persistent block
#define HPB 8           // h elements owned per block (128*8 = 1024)

// ---------------- scratch (static device globals; no dynamic alloc) ----------------
__device__ float g_target[EDIM];
__device__ float g_zc[2][4 * HDIM];   // w_ih@target + b_ih + b_hh per direction
__device__ float g_zf[2][4 * HDIM];   // w_ih@seq[first] + b_ih + b_hh per direction
__device__ int   g_meta[4];           // {fl_step, fl_tok, fr_step, fr_tok}
__device__ __align__(16) float g_hbuf[2][HDIM];              // ping-pong h
__device__ __align__(16) float g_hsl [(size_t)LSEQ * HDIM];  // left-pass hiddens (8 MB)
__device__ __align__(16) float g_prod[(size_t)LSEQ * HDIM];  // hs_l * hs_r       (8 MB)
__device__ float g_beta[LSEQ];
__device__ float g_alfa[LSEQ];
__device__ float g_s[HDIM];
__device__ unsigned g_ctr = 0;        // central barrier counter (reset by prep each launch)

// ---------------- math helpers ----------------
__device__ __forceinline__ float sigf(float x)     { return 1.0f / (1.0f + __expf(-x)); }
__device__ __forceinline__ float tanhfast(float x) { return 1.0f - 2.0f / (1.0f + __expf(2.0f * x)); }
__device__ __forceinline__ unsigned ld_acq(const unsigned* p) {
    unsigned v;
    asm volatile("ld.acquire.gpu.u32 %0, [%1];" : "=r"(v) : "l"(p) : "memory");
    return v;
}
__device__ __forceinline__ void red_release_add(unsigned* p, unsigned v) {
    asm volatile("red.release.gpu.global.add.u32 [%0], %1;" :: "l"(p), "r"(v) : "memory");
}
// packed f32x2 FMA (Blackwell): d = a*b + c elementwise on 2 packed floats
__device__ __forceinline__ unsigned long long ffma2(unsigned long long a,
                                                    unsigned long long b,
                                                    unsigned long long c) {
    unsigned long long d;
    asm("fma.rn.f32x2 %0, %1, %2, %3;" : "=l"(d) : "l"(a), "l"(b), "l"(c));
    return d;
}
__device__ __forceinline__ float2 unpack2(unsigned long long v) {
    float2 f;
    asm("mov.b64 {%0, %1}, %2;" : "=f"(f.x), "=f"(f.y) : "l"(v));
    return f;
}

// ---------------- kernel A: target mean, meta scalars, init state ----------------
__global__ void prep_kernel(const int* __restrict__ x, const int* __restrict__ ts,
                            const int* __restrict__ te, const float* __restrict__ emb) {
    int start = ts[0], end = te[0];
    int tid = blockIdx.x * blockDim.x + threadIdx.x;   // 0..1023
    float s = 0.0f;
    for (int t = start; t <= end; t++)
        s += emb[(size_t)x[t] * EDIM + tid];
    g_target[tid] = s / (float)(end - start + 1);
    g_beta[tid] = 0.0f;
    g_beta[1024 + tid] = 0.0f;
    g_s[tid] = 0.0f;
    g_hbuf[0][tid] = 0.0f;          // step-0 input h = 0
    if (tid == 0) {
        g_ctr = 0;                  // reset barrier counter every launch (graph replays!)
        int fl = (start > 0) ? 0 : (end + 1);
        g_meta[0] = (fl < LSEQ) ? fl : -1;
        g_meta[1] = (fl < LSEQ) ? fl : 0;
        int frs, frt;
        if (end < LSEQ - 1)      { frs = 0;            frt = LSEQ - 1;  }
        else if (start > 0)      { frs = LSEQ - start; frt = start - 1; }
        else                     { frs = -1;           frt = 0;         }
        g_meta[2] = frs; g_meta[3] = frt;
    }
}

// ---------------- kernel B: z vectors (4 matvecs 4096x1024), one block per output row ----
__global__ void zvec_kernel(const int* __restrict__ x, const float* __restrict__ emb,
                            const float* __restrict__ wil, const float* __restrict__ bil,
                            const float* __restrict__ bhl,
                            const float* __restrict__ wir, const float* __restrict__ bir,
                            const float* __restrict__ bhr) {
    int bid = blockIdx.x;
    int dir = bid >> 12;           // 0: left, 1: right
    int row = bid & 4095;
    const float* wi = dir ? wir : wil;
    const float* bi = dir ? bir : bil;
    const float* bh = dir ? bhr : bhl;
    int tokpos = dir ? g_meta[3] : g_meta[1];
    int tok = x[tokpos];
    const float* wrow = wi + (size_t)row * EDIM;
    const float* trow = emb + (size_t)tok * EDIM;
    int tid = threadIdx.x;
    float sc = 0.0f, sf = 0.0f;
    for (int e = tid; e < EDIM; e += 128) {
        float wv = wrow[e];
        sc += wv * g_target[e];
        sf += wv * trow[e];
    }
    #pragma unroll
    for (int off = 16; off; off >>= 1) {
        sc += __shfl_xor_sync(0xffffffffu, sc, off);
        sf += __shfl_xor_sync(0xffffffffu, sf, off);
    }
    __shared__ float r1[4], r2[4];
    int wid = tid >> 5, lane = tid & 31;
    if (lane == 0) { r1[wid] = sc; r2[wid] = sf; }
    __syncthreads();
    if (tid == 0) {
        float bb = bi[row] + bh[row];
        g_zc[dir][row] = r1[0] + r1[1] + r1[2] + r1[3] + bb;
        g_zf[dir][row] = r2[0] + r2[1] + r2[2] + r2[3] + bb;
    }
}

// ---------------- kernel C: persistent LSTM recurrence (both directions) ----------------
// 128 blocks x 256 threads, all resident. Weights in registers as packed f32x2 pairs.
// Central barrier: RED.release +1 per block, one poller per block. Ping-pong h buffers
// (safe under a per-step full barrier: readers of buf[p] always finish before any
// writer of buf[p] passes the next barrier).
__global__ void __launch_bounds__(TB, 1)
lstm_kernel(const float* __restrict__ whl, const float* __restrict__ whr) {
    __shared__ float rs[32];
    __shared__ float zc_s[32], zf_s[32];
    __shared__ float c_s[HPB];
    __shared__ __align__(16) float sm_h[HDIM];

    const int tid  = threadIdx.x;
    const int lane = tid & 31;
    const int w    = tid >> 5;
    const int hbase = blockIdx.x * HPB;

    if (tid < HPB) c_s[tid] = 0.0f;

    unsigned tgt = 0;
    ulonglong2 wv[4][8];
    for (int dir = 0; dir < 2; dir++) {
        const float* W = dir ? whr : whl;
        // load this thread's 128 weights into registers (as packed f32x2 pairs)
        #pragma unroll
        for (int r = 0; r < 4; r++) {
            int lr = 4 * w + r;
            int q = lr >> 3, k = lr & 7;
            const ulonglong2* wrow =
                (const ulonglong2*)(W + (size_t)(q * HDIM + hbase + k) * HDIM);
            #pragma unroll
            for (int j = 0; j < 8; j++) wv[r][j] = wrow[j * 32 + lane];
        }
        if (tid < 32) {
            int q = tid >> 3, k = tid & 7;
            zc_s[tid] = g_zc[dir][q * HDIM + hbase + k];
            zf_s[tid] = g_zf[dir][q * HDIM + hbase + k];
        }
        const int special = dir ? g_meta[2] : g_meta[0];
        __syncthreads();

        for (int step = 0; step < LSEQ; step++) {
            const unsigned g = (unsigned)(dir * LSEQ + step);

            // stage h into SMEM: one 4 KB cooperative L2 read per block
            {
                float4 v = __ldcg(&((const float4*)g_hbuf[g & 1u])[tid]);
                ((float4*)sm_h)[tid] = v;
            }
            __syncthreads();

            // 4 gate-rows per warp: packed-FMA dot products over SMEM h
            const ulonglong2* hp = (const ulonglong2*)sm_h;
            ulonglong2 hv[8];
            #pragma unroll
            for (int j = 0; j < 8; j++) hv[j] = hp[j * 32 + lane];

            #pragma unroll
            for (int r = 0; r < 4; r++) {
                unsigned long long a0 = 0ull, a1 = 0ull;
                #pragma unroll
                for (int j = 0; j < 8; j++) {
                    a0 = ffma2(wv[r][j].x, hv[j].x, a0);
                    a1 = ffma2(wv[r][j].y, hv[j].y, a1);
                }
                float2 p = unpack2(a0), q2 = unpack2(a1);
                float a = (p.x + p.y) + (q2.x + q2.y);
                #pragma unroll
                for (int off = 16; off; off >>= 1)
                    a += __shfl_xor_sync(0xffffffffu, a, off);
                if (lane == 0) rs[4 * w + r] = a;
            }
            __syncthreads();

            if (tid < HPB) {
                const float* z = (step == special) ? zf_s : zc_s;
                int k = tid;
                float pi = rs[k]      + z[k];
                float pf = rs[8 + k]  + z[8 + k];
                float pg = rs[16 + k] + z[16 + k];
                float po = rs[24 + k] + z[24 + k];
                float gi = sigf(pi), gf = sigf(pf), gg = tanhfast(pg), go = sigf(po);
                float c = gf * c_s[k] + gi * gg;
                c_s[k] = c;
                float h = go * tanhfast(c);
                __stcg(&g_hbuf[(g + 1u) & 1u][hbase + k], h);
                size_t off = (size_t)step * HDIM + hbase + k;
                if (dir == 0) g_hsl[off] = h;
                else          g_prod[off] = h * g_hsl[off];
            }
            __syncthreads();

            // central barrier: release-RED then single poller per block
            tgt += GB;
            if (tid == 0) {
                red_release_add(&g_ctr, 1u);
                while (ld_acq(&g_ctr) < tgt) {}
            }
            __syncthreads();
        }
    }
}

// ---------------- kernel D: beta[t] = sum_j u[j]*tanh(lin1_w[j,:]·prod[t,:] + b[j]) ------
__global__ void beta_kernel(const float* __restrict__ l1w, const float* __restrict__ l1b,
                            const float* __restrict__ u) {
    __shared__ float sA[32][33];
    __shared__ __align__(16) float sBT[32][128];
    __shared__ float red[8][32];

    const int tid = threadIdx.x;
    const int t0 = blockIdx.x * 32;
    const int j0 = blockIdx.y * 128;
    const int t  = tid & 31;
    const int jg = tid >> 5;

    float acc[16];
    #pragma unroll
    for (int m = 0; m < 16; m++) acc[m] = 0.0f;

    const float4* prod4 = (const float4*)g_prod;

    for (int kc = 0; kc < HDIM; kc += 32) {
        {
            int tl = tid >> 3;
            int k0 = (tid & 7) * 4;
            float4 v = prod4[(size_t)(t0 + tl) * 256 + (kc >> 2) + (tid & 7)];
            sA[tl][k0 + 0] = v.x; sA[tl][k0 + 1] = v.y;
            sA[tl][k0 + 2] = v.z; sA[tl][k0 + 3] = v.w;
        }
        {
            int jj = tid >> 1;
            int koff = (tid & 1) * 16;
            const float4* wr = (const float4*)(l1w + (size_t)(j0 + jj) * HDIM + kc + koff);
            #pragma unroll
            for (int q4 = 0; q4 < 4; q4++) {
                float4 v = wr[q4];
                sBT[koff + q4 * 4 + 0][jj] = v.x;
                sBT[koff + q4 * 4 + 1][jj] = v.y;
                sBT[koff + q4 * 4 + 2][jj] = v.z;
                sBT[koff + q4 * 4 + 3][jj] = v.w;
            }
        }
        __syncthreads();
        #pragma unroll 8
        for (int k = 0; k < 32; k++) {
            float a = sA[t][k];
            const float4* brow = (const float4*)(&sBT[k][jg * 16]);
            float4 b0 = brow[0], b1 = brow[1], b2 = brow[2], b3 = brow[3];
            acc[0]  += a * b0.x; acc[1]  += a * b0.y; acc[2]  += a * b0.z; acc[3]  += a * b0.w;
            acc[4]  += a * b1.x; acc[5]  += a * b1.y; acc[6]  += a * b1.z; acc[7]  += a * b1.w;
            acc[8]  += a * b2.x; acc[9]  += a * b2.y; acc[10] += a * b2.z; acc[11] += a * b2.w;
            acc[12] += a * b3.x; acc[13] += a * b3.y; acc[14] += a * b3.z; acc[15] += a * b3.w;
        }
        __syncthreads();
    }

    float partial = 0.0f;
    #pragma unroll
    for (int m = 0; m < 16; m++) {
        int j = j0 + jg * 16 + m;
        float val = acc[m] + l1b[j];
        partial += tanhfast(val) * u[j];
    }
    red[jg][t] = partial;
    __syncthreads();
    if (tid < 32) {
        float s = 0.0f;
        #pragma unroll
        for (int g2 = 0; g2 < 8; g2++) s += red[g2][tid];
        atomicAdd(&g_beta[t0 + tid], s);
    }
}

// ---------------- kernel E: softmax over beta[2048] -> alfa ----------------
__global__ void softmax_kernel() {
    __shared__ float sm[256];
    int tid = threadIdx.x;
    float v[8];
    float mx = -1e30f;
    #pragma unroll
    for (int i = 0; i < 8; i++) { v[i] = g_beta[tid * 8 + i]; mx = fmaxf(mx, v[i]); }
    sm[tid] = mx; __syncthreads();
    for (int s = 128; s; s >>= 1) { if (tid < s) sm[tid] = fmaxf(sm[tid], sm[tid + s]); __syncthreads(); }
    mx = sm[0]; __syncthreads();
    float sum = 0.0f;
    #pragma unroll
    for (int i = 0; i < 8; i++) { v[i] = __expf(v[i] - mx); sum += v[i]; }
    sm[tid] = sum; __syncthreads();
    for (int s = 128; s; s >>= 1) { if (tid < s) sm[tid] += sm[tid + s]; __syncthreads(); }
    float inv = 1.0f / sm[0];
    #pragma unroll
    for (int i = 0; i < 8; i++) g_alfa[tid * 8 + i] = v[i] * inv;
}

// ---------------- kernel F: s[j] = sum_t alfa[t] * prod[t,j] ----------------
__global__ void sred_kernel() {
    int tid = threadIdx.x;
    int t0 = blockIdx.x * 64;
    float4 acc = make_float4(0.f, 0.f, 0.f, 0.f);
    const float4* p4 = (const float4*)g_prod;
    for (int t = 0; t < 64; t++) {
        float a = g_alfa[t0 + t];
        float4 p = p4[(size_t)(t0 + t) * 256 + tid];
        acc.x += a * p.x; acc.y += a * p.y; acc.z += a * p.z; acc.w += a * p.w;
    }
    atomicAdd(&g_s[tid * 4 + 0], acc.x);
    atomicAdd(&g_s[tid * 4 + 1], acc.y);
    atomicAdd(&g_s[tid * 4 + 2], acc.z);
    atomicAdd(&g_s[tid * 4 + 3], acc.w);
}

// ---------------- kernel G: out[p] = s · lin2_w[p,:] + lin2_b[p], p=0..2 ----------------
__global__ void final_kernel(const float* __restrict__ l2w, const float* __restrict__ l2b,
                             float* __restrict__ out) {
    int wp = threadIdx.x >> 5, lane = threadIdx.x & 31;
    if (wp < 3) {
        float s = 0.0f;
        for (int j = lane; j < HDIM; j += 32)
            s += g_s[j] * l2w[wp * HDIM + j];
        #pragma unroll
        for (int off = 16; off; off >>= 1) s += __shfl_xor_sync(0xffffffffu, s, off);
        if (lane == 0) out[wp] = s + l2b[wp];
    }
}

// ---------------- launch ----------------
extern "C" void kernel_launch(void* const* d_in, const int* in_sizes, int n_in,
                              void* d_out, int out_size) {
    (void)in_sizes; (void)n_in; (void)out_size;
    const int*   x   = (const int*)d_in[0];
    const int*   ts  = (const int*)d_in[1];
    const int*   te  = (const int*)d_in[2];
    const float* emb = (const float*)d_in[3];
    const float* wil = (const float*)d_in[4];
    const float* whl = (const float*)d_in[5];
    const float* bil = (const float*)d_in[6];
    const float* bhl = (const float*)d_in[7];
    const float* wir = (const float*)d_in[8];
    const float* whr = (const float*)d_in[9];
    const float* bir = (const float*)d_in[10];
    const float* bhr = (const float*)d_in[11];
    const float* l1w = (const float*)d_in[12];
    const float* l1b = (const float*)d_in[13];
    const float* u   = (const float*)d_in[14];
    const float* l2w = (const float*)d_in[15];
    const float* l2b = (const float*)d_in[16];
    float* out = (float*)d_out;

    prep_kernel<<<8, 128>>>(x, ts, te, emb);
    zvec_kernel<<<8192, 128>>>(x, emb, wil, bil, bhl, wir, bir, bhr);
    lstm_kernel<<<GB, TB>>>(whl, whr);
    beta_kernel<<<dim3(LSEQ / 32, HDIM / 128), 256>>>(l1w, l1b, u);
    softmax_kernel<<<1, 256>>>();
    sred_kernel<<<32, 256>>>();
    final_kernel<<<1, 128>>>(l2w, l2b, out);
}

// round 7
// speedup vs baseline: 3.2045x; 1.0740x over previous
#include <cuda_runtime.h>
#include <cstdint>

// Problem constants (fixed shapes from setup_inputs)
#define LSEQ 2048
#define HDIM 1024
#define EDIM 1024
#define GB 128          // persistent blocks (1 per SM, all co-resident)
#define TB 256          // threads per persistent block
#define HPB 8           // h elements owned per block (128*8 = 1024)

// ---------------- scratch (static device globals; no dynamic alloc) ----------------
__device__ float g_target[EDIM];
__device__ float g_zc[2][4 * HDIM];   // w_ih@target + b_ih + b_hh per direction
__device__ float g_zf[2][4 * HDIM];   // w_ih@seq[first] + b_ih + b_hh per direction
__device__ int   g_meta[4];           // {fl_step, fl_tok, fr_step, fr_tok}
__device__ __align__(16) float g_hbuf[2][HDIM];              // ping-pong h
__device__ __align__(16) float g_hsl [(size_t)LSEQ * HDIM];  // left-pass hiddens (8 MB)
__device__ __align__(16) float g_prod[(size_t)LSEQ * HDIM];  // hs_l * hs_r       (8 MB)
__device__ float g_beta[LSEQ];
__device__ float g_alfa[LSEQ];
__device__ float g_s[HDIM];
__device__ unsigned g_ctrs[4 * 32];   // 4 barrier counters, 128B apart (different L2 lines)

// ---------------- math helpers ----------------
__device__ __forceinline__ float sigf(float x)     { return 1.0f / (1.0f + __expf(-x)); }
__device__ __forceinline__ float tanhfast(float x) { return 1.0f - 2.0f / (1.0f + __expf(2.0f * x)); }
__device__ __forceinline__ unsigned ld_acq(const unsigned* p) {
    unsigned v;
    asm volatile("ld.acquire.gpu.u32 %0, [%1];" : "=r"(v) : "l"(p) : "memory");
    return v;
}
__device__ __forceinline__ void red_release_add(unsigned* p, unsigned v) {
    asm volatile("red.release.gpu.global.add.u32 [%0], %1;" :: "l"(p), "r"(v) : "memory");
}
// packed f32x2 FMA (Blackwell): d = a*b + c elementwise on 2 packed floats
__device__ __forceinline__ unsigned long long ffma2(unsigned long long a,
                                                    unsigned long long b,
                                                    unsigned long long c) {
    unsigned long long d;
    asm("fma.rn.f32x2 %0, %1, %2, %3;" : "=l"(d) : "l"(a), "l"(b), "l"(c));
    return d;
}
__device__ __forceinline__ float2 unpack2(unsigned long long v) {
    float2 f;
    asm("mov.b64 {%0, %1}, %2;" : "=f"(f.x), "=f"(f.y) : "l"(v));
    return f;
}

// ---------------- kernel A: target mean, meta scalars, init state ----------------
__global__ void prep_kernel(const int* __restrict__ x, const int* __restrict__ ts,
                            const int* __restrict__ te, const float* __restrict__ emb) {
    int start = ts[0], end = te[0];
    int tid = blockIdx.x * blockDim.x + threadIdx.x;   // 0..1023
    float s = 0.0f;
    for (int t = start; t <= end; t++)
        s += emb[(size_t)x[t] * EDIM + tid];
    g_target[tid] = s / (float)(end - start + 1);
    g_beta[tid] = 0.0f;
    g_beta[1024 + tid] = 0.0f;
    g_s[tid] = 0.0f;
    g_hbuf[0][tid] = 0.0f;          // step-0 input h = 0
    if (tid < 4 * 32) g_ctrs[tid] = 0;   // reset barrier counters every launch (graph replays)
    if (tid == 0) {
        int fl = (start > 0) ? 0 : (end + 1);
        g_meta[0] = (fl < LSEQ) ? fl : -1;
        g_meta[1] = (fl < LSEQ) ? fl : 0;
        int frs, frt;
        if (end < LSEQ - 1)      { frs = 0;            frt = LSEQ - 1;  }
        else if (start > 0)      { frs = LSEQ - start; frt = start - 1; }
        else                     { frs = -1;           frt = 0;         }
        g_meta[2] = frs; g_meta[3] = frt;
    }
}

// ---------------- kernel B: z vectors (4 matvecs 4096x1024), one block per output row ----
__global__ void zvec_kernel(const int* __restrict__ x, const float* __restrict__ emb,
                            const float* __restrict__ wil, const float* __restrict__ bil,
                            const float* __restrict__ bhl,
                            const float* __restrict__ wir, const float* __restrict__ bir,
                            const float* __restrict__ bhr) {
    int bid = blockIdx.x;
    int dir = bid >> 12;           // 0: left, 1: right
    int row = bid & 4095;
    const float* wi = dir ? wir : wil;
    const float* bi = dir ? bir : bil;
    const float* bh = dir ? bhr : bhl;
    int tokpos = dir ? g_meta[3] : g_meta[1];
    int tok = x[tokpos];
    const float* wrow = wi + (size_t)row * EDIM;
    const float* trow = emb + (size_t)tok * EDIM;
    int tid = threadIdx.x;
    float sc = 0.0f, sf = 0.0f;
    for (int e = tid; e < EDIM; e += 128) {
        float wv = wrow[e];
        sc += wv * g_target[e];
        sf += wv * trow[e];
    }
    #pragma unroll
    for (int off = 16; off; off >>= 1) {
        sc += __shfl_xor_sync(0xffffffffu, sc, off);
        sf += __shfl_xor_sync(0xffffffffu, sf, off);
    }
    __shared__ float r1[4], r2[4];
    int wid = tid >> 5, lane = tid & 31;
    if (lane == 0) { r1[wid] = sc; r2[wid] = sf; }
    __syncthreads();
    if (tid == 0) {
        float bb = bi[row] + bh[row];
        g_zc[dir][row] = r1[0] + r1[1] + r1[2] + r1[3] + bb;
        g_zf[dir][row] = r2[0] + r2[1] + r2[2] + r2[3] + bb;
    }
}

// ---------------- kernel C: persistent LSTM recurrence (both directions) ----------------
// 128 blocks x 256 threads, all resident. Weights in registers as packed f32x2 pairs.
// Per step: stage h -> SMEM, packed-FMA dots + shfl reduce -> rs, then warp 0 alone does
// gates (spread over 32 lanes), publishes h, arrives on 4 padded counters, and polls.
__global__ void __launch_bounds__(TB, 1)
lstm_kernel(const float* __restrict__ whl, const float* __restrict__ whr) {
    __shared__ float rs[32];
    __shared__ __align__(16) float sm_h[HDIM];

    const int tid  = threadIdx.x;
    const int lane = tid & 31;
    const int w    = tid >> 5;
    const int hbase = blockIdx.x * HPB;

    // warp-0 per-lane gate state: lane t handles gate q=t>>3, element k=t&7
    const int q = lane >> 3, k = lane & 7;
    const bool is_g = (q == 2);
    float c_reg = 0.0f;                 // lanes 0..7 carry c (persists across directions)
    unsigned tgt32 = 0;

    ulonglong2 wv[4][8];
    for (int dir = 0; dir < 2; dir++) {
        const float* W = dir ? whr : whl;
        // load this thread's 128 weights into registers (as packed f32x2 pairs)
        #pragma unroll
        for (int r = 0; r < 4; r++) {
            int lr = 4 * w + r;
            int qq = lr >> 3, kk = lr & 7;
            const ulonglong2* wrow =
                (const ulonglong2*)(W + (size_t)(qq * HDIM + hbase + kk) * HDIM);
            #pragma unroll
            for (int j = 0; j < 8; j++) wv[r][j] = wrow[j * 32 + lane];
        }
        float zc_r = 0.0f, zf_r = 0.0f;
        if (w == 0) {
            zc_r = g_zc[dir][q * HDIM + hbase + k];
            zf_r = g_zf[dir][q * HDIM + hbase + k];
        }
        const int special = dir ? g_meta[2] : g_meta[0];
        __syncthreads();

        for (int step = 0; step < LSEQ; step++) {
            const unsigned g = (unsigned)(dir * LSEQ + step);
            const size_t rowoff = (size_t)step * HDIM + hbase;

            // stage h into SMEM: one 4 KB cooperative L2 read per block
            {
                float4 v = __ldcg(&((const float4*)g_hbuf[g & 1u])[tid]);
                ((float4*)sm_h)[tid] = v;
            }
            // prefetch left-pass h for the prod store (off critical path)
            float hsl_pref = 0.0f;
            if (dir == 1 && w == 0 && lane < HPB)
                hsl_pref = __ldcg(&g_hsl[rowoff + lane]);
            __syncthreads();

            // 4 gate-rows per warp: packed-FMA dot products over SMEM h
            const ulonglong2* hp = (const ulonglong2*)sm_h;
            ulonglong2 hv[8];
            #pragma unroll
            for (int j = 0; j < 8; j++) hv[j] = hp[j * 32 + lane];

            #pragma unroll
            for (int r = 0; r < 4; r++) {
                unsigned long long a0 = 0ull, a1 = 0ull;
                #pragma unroll
                for (int j = 0; j < 8; j++) {
                    a0 = ffma2(wv[r][j].x, hv[j].x, a0);
                    a1 = ffma2(wv[r][j].y, hv[j].y, a1);
                }
                float2 p = unpack2(a0), q2 = unpack2(a1);
                float a = (p.x + p.y) + (q2.x + q2.y);
                #pragma unroll
                for (int off = 16; off; off >>= 1)
                    a += __shfl_xor_sync(0xffffffffu, a, off);
                if (lane == 0) rs[4 * w + r] = a;
            }
            __syncthreads();

            // ---- warp 0 only: gates, publish, arrive, poll ----
            if (w == 0) {
                float pre = rs[lane] + ((step == special) ? zf_r : zc_r);
                // single-exp path: tanh(x) = 2*sigmoid(2x) - 1
                float xin = is_g ? (2.0f * pre) : pre;
                float sg = sigf(xin);
                float act = is_g ? (2.0f * sg - 1.0f) : sg;
                float gi = __shfl_sync(0xffffffffu, act, k);
                float gf = __shfl_sync(0xffffffffu, act, k + 8);
                float gg = __shfl_sync(0xffffffffu, act, k + 16);
                float go = __shfl_sync(0xffffffffu, act, k + 24);
                float h = 0.0f;
                if (lane < HPB) {
                    float c = gf * c_reg + gi * gg;
                    c_reg = c;
                    h = go * tanhfast(c);
                    __stcg(&g_hbuf[(g + 1u) & 1u][hbase + lane], h);
                }
                __syncwarp();
                if (lane == 0) {
                    __threadfence();   // order h stores (whole SM) before the arrive
                    red_release_add(&g_ctrs[(blockIdx.x & 3) * 32], 1u);
                }
                // non-critical stores after the arrive
                if (lane < HPB) {
                    if (dir == 0) g_hsl[rowoff + lane] = h;
                    else          g_prod[rowoff + lane] = h * hsl_pref;
                }
                // poll: 4 padded counters, 32 arrivals each per step
                tgt32 += 32;
                if (lane < 4) { while (ld_acq(&g_ctrs[lane * 32]) < tgt32) {} }
                __syncwarp();
            } else {
                tgt32 += 32;           // keep warp-uniform state consistent
            }
            __syncthreads();
        }
    }
}

// ---------------- kernel D: beta[t] = sum_j u[j]*tanh(lin1_w[j,:]·prod[t,:] + b[j]) ------
__global__ void beta_kernel(const float* __restrict__ l1w, const float* __restrict__ l1b,
                            const float* __restrict__ u) {
    __shared__ float sA[32][33];
    __shared__ __align__(16) float sBT[32][128];
    __shared__ float red[8][32];

    const int tid = threadIdx.x;
    const int t0 = blockIdx.x * 32;
    const int j0 = blockIdx.y * 128;
    const int t  = tid & 31;
    const int jg = tid >> 5;

    float acc[16];
    #pragma unroll
    for (int m = 0; m < 16; m++) acc[m] = 0.0f;

    const float4* prod4 = (const float4*)g_prod;

    for (int kc = 0; kc < HDIM; kc += 32) {
        {
            int tl = tid >> 3;
            int k0 = (tid & 7) * 4;
            float4 v = prod4[(size_t)(t0 + tl) * 256 + (kc >> 2) + (tid & 7)];
            sA[tl][k0 + 0] = v.x; sA[tl][k0 + 1] = v.y;
            sA[tl][k0 + 2] = v.z; sA[tl][k0 + 3] = v.w;
        }
        {
            int jj = tid >> 1;
            int koff = (tid & 1) * 16;
            const float4* wr = (const float4*)(l1w + (size_t)(j0 + jj) * HDIM + kc + koff);
            #pragma unroll
            for (int q4 = 0; q4 < 4; q4++) {
                float4 v = wr[q4];
                sBT[koff + q4 * 4 + 0][jj] = v.x;
                sBT[koff + q4 * 4 + 1][jj] = v.y;
                sBT[koff + q4 * 4 + 2][jj] = v.z;
                sBT[koff + q4 * 4 + 3][jj] = v.w;
            }
        }
        __syncthreads();
        #pragma unroll 8
        for (int kk = 0; kk < 32; kk++) {
            float a = sA[t][kk];
            const float4* brow = (const float4*)(&sBT[kk][jg * 16]);
            float4 b0 = brow[0], b1 = brow[1], b2 = brow[2], b3 = brow[3];
            acc[0]  += a * b0.x; acc[1]  += a * b0.y; acc[2]  += a * b0.z; acc[3]  += a * b0.w;
            acc[4]  += a * b1.x; acc[5]  += a * b1.y; acc[6]  += a * b1.z; acc[7]  += a * b1.w;
            acc[8]  += a * b2.x; acc[9]  += a * b2.y; acc[10] += a * b2.z; acc[11] += a * b2.w;
            acc[12] += a * b3.x; acc[13] += a * b3.y; acc[14] += a * b3.z; acc[15] += a * b3.w;
        }
        __syncthreads();
    }

    float partial = 0.0f;
    #pragma unroll
    for (int m = 0; m < 16; m++) {
        int j = j0 + jg * 16 + m;
        float val = acc[m] + l1b[j];
        partial += tanhfast(val) * u[j];
    }
    red[jg][t] = partial;
    __syncthreads();
    if (tid < 32) {
        float s = 0.0f;
        #pragma unroll
        for (int g2 = 0; g2 < 8; g2++) s += red[g2][tid];
        atomicAdd(&g_beta[t0 + tid], s);
    }
}

// ---------------- kernel E: softmax over beta[2048] -> alfa ----------------
__global__ void softmax_kernel() {
    __shared__ float sm[256];
    int tid = threadIdx.x;
    float v[8];
    float mx = -1e30f;
    #pragma unroll
    for (int i = 0; i < 8; i++) { v[i] = g_beta[tid * 8 + i]; mx = fmaxf(mx, v[i]); }
    sm[tid] = mx; __syncthreads();
    for (int s = 128; s; s >>= 1) { if (tid < s) sm[tid] = fmaxf(sm[tid], sm[tid + s]); __syncthreads(); }
    mx = sm[0]; __syncthreads();
    float sum = 0.0f;
    #pragma unroll
    for (int i = 0; i < 8; i++) { v[i] = __expf(v[i] - mx); sum += v[i]; }
    sm[tid] = sum; __syncthreads();
    for (int s = 128; s; s >>= 1) { if (tid < s) sm[tid] += sm[tid + s]; __syncthreads(); }
    float inv = 1.0f / sm[0];
    #pragma unroll
    for (int i = 0; i < 8; i++) g_alfa[tid * 8 + i] = v[i] * inv;
}

// ---------------- kernel F: s[j] = sum_t alfa[t] * prod[t,j] ----------------
__global__ void sred_kernel() {
    int tid = threadIdx.x;
    int t0 = blockIdx.x * 64;
    float4 acc = make_float4(0.f, 0.f, 0.f, 0.f);
    const float4* p4 = (const float4*)g_prod;
    for (int t = 0; t < 64; t++) {
        float a = g_alfa[t0 + t];
        float4 p = p4[(size_t)(t0 + t) * 256 + tid];
        acc.x += a * p.x; acc.y += a * p.y; acc.z += a * p.z; acc.w += a * p.w;
    }
    atomicAdd(&g_s[tid * 4 + 0], acc.x);
    atomicAdd(&g_s[tid * 4 + 1], acc.y);
    atomicAdd(&g_s[tid * 4 + 2], acc.z);
    atomicAdd(&g_s[tid * 4 + 3], acc.w);
}

// ---------------- kernel G: out[p] = s · lin2_w[p,:] + lin2_b[p], p=0..2 ----------------
__global__ void final_kernel(const float* __restrict__ l2w, const float* __restrict__ l2b,
                             float* __restrict__ out) {
    int wp = threadIdx.x >> 5, lane = threadIdx.x & 31;
    if (wp < 3) {
        float s = 0.0f;
        for (int j = lane; j < HDIM; j += 32)
            s += g_s[j] * l2w[wp * HDIM + j];
        #pragma unroll
        for (int off = 16; off; off >>= 1) s += __shfl_xor_sync(0xffffffffu, s, off);
        if (lane == 0) out[wp] = s + l2b[wp];
    }
}

// ---------------- launch ----------------
extern "C" void kernel_launch(void* const* d_in, const int* in_sizes, int n_in,
                              void* d_out, int out_size) {
    (void)in_sizes; (void)n_in; (void)out_size;
    const int*   x   = (const int*)d_in[0];
    const int*   ts  = (const int*)d_in[1];
    const int*   te  = (const int*)d_in[2];
    const float* emb = (const float*)d_in[3];
    const float* wil = (const float*)d_in[4];
    const float* whl = (const float*)d_in[5];
    const float* bil = (const float*)d_in[6];
    const float* bhl = (const float*)d_in[7];
    const float* wir = (const float*)d_in[8];
    const float* whr = (const float*)d_in[9];
    const float* bir = (const float*)d_in[10];
    const float* bhr = (const float*)d_in[11];
    const float* l1w = (const float*)d_in[12];
    const float* l1b = (const float*)d_in[13];
    const float* u   = (const float*)d_in[14];
    const float* l2w = (const float*)d_in[15];
    const float* l2b = (const float*)d_in[16];
    float* out = (float*)d_out;

    prep_kernel<<<8, 128>>>(x, ts, te, emb);
    zvec_kernel<<<8192, 128>>>(x, emb, wil, bil, bhl, wir, bir, bhr);
    lstm_kernel<<<GB, TB>>>(whl, whr);
    beta_kernel<<<dim3(LSEQ / 32, HDIM / 128), 256>>>(l1w, l1b, u);
    softmax_kernel<<<1, 256>>>();
    sred_kernel<<<32, 256>>>();
    final_kernel<<<1, 128>>>(l2w, l2b, out);
}